// round 16
// baseline (speedup 1.0000x reference)
#include <cuda_runtime.h>
#include <cuda_fp16.h>
#include <stdint.h>
#include <math.h>

#define BATCH  65536
#define D_DIM  256
#define W_DIM  1024
#define MTILE  64
#define NTHREADS 256
#define CW     128
#define NCHUNK (W_DIM / CW)    // 8
#define NGRID  (BATCH / MTILE) // 1024
#define WSCALE 64.0f
#define WINV   (1.0f / 64.0f)

// device scratch: weights scaled fp16 (z converted in-kernel)
__device__ __align__(16) __half g_w1s[W_DIM * D_DIM];   // W1 * 64
__device__ __align__(16) __half g_w2s[D_DIM * W_DIM];   // W2 * 64
__device__ float g_M[W_DIM];

// ---------------- SMEM layout (bytes), XOR-swizzled, pad-free ----------------
// z  : [64][512B]   (256 fp16/row)
// W1 : [128][512B]  chunk rows = W-col j
// W2 : [256][256B]  chunk (128 fp16/row)
// h  : [64][256B]
#define Z_S    0
#define W1_S   32768
#define W2_S   98304
#define H_S    163840
#define TR_OFF 180224
#define S_TOTAL 180480

// ---------------- PTX helpers ----------------
__device__ __forceinline__ uint32_t smem_u32(const void* p) {
    uint32_t a;
    asm("{ .reg .u64 t; cvta.to.shared.u64 t, %1; cvt.u32.u64 %0, t; }" : "=r"(a) : "l"(p));
    return a;
}
#define CP_ASYNC16(d, s) \
    asm volatile("cp.async.cg.shared.global [%0], [%1], 16;" :: "r"(d), "l"(s))
#define CP_COMMIT() asm volatile("cp.async.commit_group;")
#define CP_WAIT0()  asm volatile("cp.async.wait_group 0;")
#define CP_WAIT1()  asm volatile("cp.async.wait_group 1;")

#define LDSM4(r, addr) \
    asm volatile("ldmatrix.sync.aligned.m8n8.x4.shared.b16 {%0,%1,%2,%3}, [%4];" \
        : "=r"((r)[0]), "=r"((r)[1]), "=r"((r)[2]), "=r"((r)[3]) : "r"(addr))

__device__ __forceinline__ void mma_f16(float* c, const uint32_t* a, uint32_t b0, uint32_t b1) {
    asm volatile(
        "mma.sync.aligned.m16n8k16.row.col.f32.f16.f16.f32 "
        "{%0,%1,%2,%3}, {%4,%5,%6,%7}, {%8,%9}, {%0,%1,%2,%3};"
        : "+f"(c[0]), "+f"(c[1]), "+f"(c[2]), "+f"(c[3])
        : "r"(a[0]), "r"(a[1]), "r"(a[2]), "r"(a[3]), "r"(b0), "r"(b1));
}

// ---------------- fused prepass: weights conv + M, ONE launch ----------------
#define WCONV_BLOCKS 256
union PackH8 { uint4 u; __half h[8]; };

__global__ void prep_kernel(const float* __restrict__ W1,
                            const float* __restrict__ W2) {
    if (blockIdx.x < WCONV_BLOCKS) {
        size_t gid = (size_t)blockIdx.x * 256 + threadIdx.x;
        const float* src;
        __half* dst;
        size_t idx;
        if (gid < 32768) { src = W1; dst = g_w1s; idx = gid; }
        else             { src = W2; dst = g_w2s; idx = gid - 32768; }
        const float4* s = reinterpret_cast<const float4*>(src);
        float4 a = s[idx * 2], b = s[idx * 2 + 1];
        float v[8] = {a.x, a.y, a.z, a.w, b.x, b.y, b.z, b.w};
        PackH8 o;
        #pragma unroll
        for (int i = 0; i < 8; i++) o.h[i] = __float2half_rn(v[i] * WSCALE);
        reinterpret_cast<uint4*>(dst)[idx] = o.u;
    } else {
        int j = blockIdx.x - WCONV_BLOCKS, i = threadIdx.x;
        float v = W1[j * D_DIM + i] * W2[(size_t)i * W_DIM + j];
        #pragma unroll
        for (int o = 16; o > 0; o >>= 1) v += __shfl_down_sync(0xffffffffu, v, o);
        __shared__ float red[8];
        if ((i & 31) == 0) red[i >> 5] = v;
        __syncthreads();
        if (i < 8) {
            float s = red[i];
            #pragma unroll
            for (int o = 4; o > 0; o >>= 1) s += __shfl_down_sync(0xffu, s, o);
            if (i == 0) g_M[j] = s;
        }
    }
}

// ---------------- copy helpers (cp.async, 256 threads, swizzled dst) ---------
// nrows x 256 fp16 (512B rows)
__device__ __forceinline__ void cp_tile512(uint32_t sdst, const __half* g, int nrows) {
    const int total = nrows * 32;
    for (int i = threadIdx.x; i < total; i += NTHREADS) {
        int r = i >> 5, cu = i & 31;
        CP_ASYNC16(sdst + r * 512 + ((cu ^ (r & 7)) << 4), g + r * 256 + cu * 8);
    }
}
// 256 rows x 128 fp16 (256B rows), src rows stride W_DIM
__device__ __forceinline__ void cp_tileW2(uint32_t sdst, const __half* g) {
    for (int i = threadIdx.x; i < 4096; i += NTHREADS) {
        int r = i >> 4, cu = i & 15;
        CP_ASYNC16(sdst + r * 256 + ((cu ^ (r & 7)) << 4), g + (size_t)r * W_DIM + cu * 8);
    }
}

// ---------------- main fused kernel (256 threads, 255-reg budget) ------------
__global__ void __launch_bounds__(NTHREADS, 1)
planar_mma_kernel(const float* __restrict__ z,
                  const float* __restrict__ b1,
                  float* __restrict__ dz_out,
                  float* __restrict__ dlog_out) {
    extern __shared__ char smem[];
    const uint32_t sb = smem_u32(smem);
    float* sTr = reinterpret_cast<float*>(smem + TR_OFF);

    const int tid  = threadIdx.x;
    const int wid  = tid >> 5;
    const int lane = tid & 31;
    const int mg   = wid >> 2;     // 0..1 : rows 32*mg .. +31
    const int ng   = wid & 3;      // GEMM1: 32 cols; GEMM2: 64 cols
    const int row0 = blockIdx.x * MTILE;

    if (tid < MTILE) sTr[tid] = 0.0f;

    // prologue: weights via cp.async; z fp32 -> fp16 converted inline
    cp_tile512(sb + W1_S, g_w1s, 128);
    cp_tileW2(sb + W2_S, g_w2s);
    CP_COMMIT();
    {
        const float4* zg = reinterpret_cast<const float4*>(z + (size_t)row0 * D_DIM);
        for (int i = tid; i < MTILE * 32; i += NTHREADS) {
            int r = i >> 5, cu = i & 31;
            float4 a = zg[r * 64 + cu * 2];
            float4 b = zg[r * 64 + cu * 2 + 1];
            float v[8] = {a.x, a.y, a.z, a.w, b.x, b.y, b.z, b.w};
            PackH8 o;
            #pragma unroll
            for (int q = 0; q < 8; q++) o.h[q] = __float2half_rn(v[q]);
            const uint32_t da = sb + Z_S + r * 512 + ((cu ^ (r & 7)) << 4);
            asm volatile("st.shared.v4.b32 [%0], {%1,%2,%3,%4};"
                :: "r"(da), "r"(o.u.x), "r"(o.u.y), "r"(o.u.z), "r"(o.u.w) : "memory");
        }
    }
    CP_WAIT0();
    __syncthreads();

    // per-lane fragment addressing (XOR swizzle; swz == lane&7 for all reads)
    const int lr    = lane & 15;
    const int kodd  = lane >> 4;
    const int brow  = (lane & 7) + ((lane >> 4) << 3);
    const int koddb = (lane >> 3) & 1;
    const int swz   = lane & 7;

    const uint32_t zbase  = sb + Z_S  + (mg * 32 + lr) * 512;
    const uint32_t w1base = sb + W1_S + (ng * 32 + brow) * 512;
    const uint32_t hbase  = sb + H_S  + (mg * 32 + lr) * 256;
    const uint32_t w2base = sb + W2_S + (ng * 64 + brow) * 256;

    float dz[2][8][4];
    #pragma unroll
    for (int a = 0; a < 2; a++)
        #pragma unroll
        for (int b = 0; b < 8; b++)
            #pragma unroll
            for (int c = 0; c < 4; c++) dz[a][b][c] = 0.0f;
    float tr4[4] = {0.f, 0.f, 0.f, 0.f};

    for (int ch = 0; ch < NCHUNK; ch++) {
        const int jc = ch * CW;

        // ---------- GEMM1: pre = z @ (64*W1chunk)^T, warp m32n32 --------------
        // explicit double-buffered fragments: LDSM(ks+1) issued before MMA(ks)
        float pre[2][4][4];
        #pragma unroll
        for (int a = 0; a < 2; a++)
            #pragma unroll
            for (int b = 0; b < 4; b++)
                #pragma unroll
                for (int c = 0; c < 4; c++) pre[a][b][c] = 0.0f;

        {
            uint32_t ah0[2][4], ah1[2][4], bh0[2][4], bh1[2][4];
            uint32_t offA = (uint32_t)(((kodd) ^ swz) << 4);
            uint32_t offB = (uint32_t)(((koddb) ^ swz) << 4);
            LDSM4(ah0[0], zbase + offA);
            LDSM4(ah1[0], zbase + 16 * 512 + offA);
            LDSM4(bh0[0], w1base + offB);
            LDSM4(bh1[0], w1base + 16 * 512 + offB);
            #pragma unroll
            for (int ks = 0; ks < 16; ks++) {
                const int cur = ks & 1, nxt = cur ^ 1;
                if (ks < 15) {
                    offA = (uint32_t)((((ks + 1) * 2 + kodd)  ^ swz) << 4);
                    offB = (uint32_t)((((ks + 1) * 2 + koddb) ^ swz) << 4);
                    LDSM4(ah0[nxt], zbase + offA);
                    LDSM4(ah1[nxt], zbase + 16 * 512 + offA);
                    LDSM4(bh0[nxt], w1base + offB);
                    LDSM4(bh1[nxt], w1base + 16 * 512 + offB);
                }
                mma_f16(pre[0][0], ah0[cur], bh0[cur][0], bh0[cur][1]);
                mma_f16(pre[0][1], ah0[cur], bh0[cur][2], bh0[cur][3]);
                mma_f16(pre[0][2], ah0[cur], bh1[cur][0], bh1[cur][1]);
                mma_f16(pre[0][3], ah0[cur], bh1[cur][2], bh1[cur][3]);
                mma_f16(pre[1][0], ah1[cur], bh0[cur][0], bh0[cur][1]);
                mma_f16(pre[1][1], ah1[cur], bh0[cur][2], bh0[cur][3]);
                mma_f16(pre[1][2], ah1[cur], bh1[cur][0], bh1[cur][1]);
                mma_f16(pre[1][3], ah1[cur], bh1[cur][2], bh1[cur][3]);
            }
        }

        // ---------- epilogue: x = pre/64 + b1; softplus -> h; trace -----------
        #pragma unroll
        for (int mf = 0; mf < 2; mf++) {
            #pragma unroll
            for (int nf = 0; nf < 4; nf++) {
                const int j0 = jc + ng * 32 + nf * 8 + 2 * (lane & 3);
                const float b10 = __ldg(&b1[j0]),   b11 = __ldg(&b1[j0 + 1]);
                const float M0  = g_M[j0],          M1  = g_M[j0 + 1];
                const int clu = ng * 4 + nf;
                #pragma unroll
                for (int bq = 0; bq < 2; bq++) {
                    float x0 = fmaf(pre[mf][nf][2 * bq],     WINV, b10);
                    float x1 = fmaf(pre[mf][nf][2 * bq + 1], WINV, b11);
                    float e0 = __expf(-fabsf(x0)), e1 = __expf(-fabsf(x1));
                    float sp0 = fmaxf(x0, 0.0f) + __logf(1.0f + e0);
                    float sp1 = fmaxf(x1, 0.0f) + __logf(1.0f + e1);
                    float i0 = __fdividef(1.0f, 1.0f + e0);
                    float i1 = __fdividef(1.0f, 1.0f + e1);
                    float sg0 = (x0 >= 0.0f) ? i0 : e0 * i0;
                    float sg1 = (x1 >= 0.0f) ? i1 : e1 * i1;
                    tr4[mf * 2 + bq] = fmaf(sg0, M0, tr4[mf * 2 + bq]);
                    tr4[mf * 2 + bq] = fmaf(sg1, M1, tr4[mf * 2 + bq]);
                    __half h0 = __float2half_rn(sp0);
                    __half h1 = __float2half_rn(sp1);
                    uint32_t phi = ((uint32_t)__half_as_ushort(h1) << 16) |
                                   (uint32_t)__half_as_ushort(h0);
                    const int rl = mg * 32 + mf * 16 + (lane >> 2) + 8 * bq;
                    const uint32_t ha = sb + H_S + rl * 256 +
                                        (((uint32_t)(clu ^ (rl & 7))) << 4) +
                                        (lane & 3) * 4;
                    asm volatile("st.shared.b32 [%0], %1;" :: "r"(ha), "r"(phi) : "memory");
                }
            }
        }

        // wait for W2(ch) (issued at tail of ch-1; only group in flight)
        CP_WAIT0();
        __syncthreads();   // AB: past GEMM1 (W1 free), h written, W2(ch) visible

        // issue W1(ch+1): hidden under GEMM2(ch)
        if (ch + 1 < NCHUNK) {
            cp_tile512(sb + W1_S, g_w1s + (size_t)(jc + CW) * D_DIM, 128);
            CP_COMMIT();
        }

        // ---------- GEMM2: dz += h @ (64*W2chunk), warp m32n64, K=128 ---------
        // double-buffered A and B fragment sets across k-steps
        {
            uint32_t ah0[2][4], ah1[2][4], bt[2][4][4];
            uint32_t offA = (uint32_t)(((kodd) ^ swz) << 4);
            uint32_t offB = (uint32_t)(((koddb) ^ swz) << 4);
            LDSM4(ah0[0], hbase + offA);
            LDSM4(ah1[0], hbase + 16 * 256 + offA);
            #pragma unroll
            for (int t = 0; t < 4; t++)
                LDSM4(bt[0][t], w2base + t * 16 * 256 + offB);
            #pragma unroll
            for (int ks = 0; ks < 8; ks++) {
                const int cur = ks & 1, nxt = cur ^ 1;
                if (ks < 7) {
                    offA = (uint32_t)((((ks + 1) * 2 + kodd)  ^ swz) << 4);
                    offB = (uint32_t)((((ks + 1) * 2 + koddb) ^ swz) << 4);
                    LDSM4(ah0[nxt], hbase + offA);
                    LDSM4(ah1[nxt], hbase + 16 * 256 + offA);
                    #pragma unroll
                    for (int t = 0; t < 4; t++)
                        LDSM4(bt[nxt][t], w2base + t * 16 * 256 + offB);
                }
                #pragma unroll
                for (int t = 0; t < 4; t++) {
                    mma_f16(dz[0][2 * t],     ah0[cur], bt[cur][t][0], bt[cur][t][1]);
                    mma_f16(dz[0][2 * t + 1], ah0[cur], bt[cur][t][2], bt[cur][t][3]);
                    mma_f16(dz[1][2 * t],     ah1[cur], bt[cur][t][0], bt[cur][t][1]);
                    mma_f16(dz[1][2 * t + 1], ah1[cur], bt[cur][t][2], bt[cur][t][3]);
                }
            }
        }

        __syncthreads();   // C: all warps past GEMM2 -> W2 buffer free

        // issue W2(ch+1): in flight across chunk boundary; wait only W1(ch+1)
        if (ch + 1 < NCHUNK) {
            cp_tileW2(sb + W2_S, g_w2s + jc + CW);
            CP_COMMIT();
            CP_WAIT1();        // W1(ch+1) done; W2(ch+1) still in flight
            __syncthreads();   // D: W1(ch+1) visible
        }
    }

    // ---------------- writeout (undo weight scale) ----------------
    #pragma unroll
    for (int mf = 0; mf < 2; mf++) {
        const int rl = mg * 32 + mf * 16 + (lane >> 2);
        #pragma unroll
        for (int nf = 0; nf < 8; nf++) {
            const int col = ng * 64 + nf * 8 + 2 * (lane & 3);
            float2 v0 = make_float2(dz[mf][nf][0] * WINV, dz[mf][nf][1] * WINV);
            float2 v1 = make_float2(dz[mf][nf][2] * WINV, dz[mf][nf][3] * WINV);
            *reinterpret_cast<float2*>(dz_out + (size_t)(row0 + rl) * D_DIM + col) = v0;
            *reinterpret_cast<float2*>(dz_out + (size_t)(row0 + rl + 8) * D_DIM + col) = v1;
        }
    }
    #pragma unroll
    for (int i = 0; i < 4; i++) {
        const int rl = mg * 32 + (i >> 1) * 16 + (lane >> 2) + 8 * (i & 1);
        atomicAdd(&sTr[rl], tr4[i]);
    }
    __syncthreads();
    if (tid < MTILE) dlog_out[row0 + tid] = -sTr[tid];
}

// ---------------------------------------------------------------------------
extern "C" void kernel_launch(void* const* d_in, const int* in_sizes, int n_in,
                              void* d_out, int out_size) {
    const float* z  = (const float*)d_in[1];
    const float* W1 = (const float*)d_in[2];
    const float* b1 = (const float*)d_in[3];
    const float* W2 = (const float*)d_in[4];

    float* dz   = (float*)d_out;
    float* dlog = dz + (size_t)BATCH * D_DIM;

    prep_kernel<<<WCONV_BLOCKS + W_DIM, 256>>>(W1, W2);

    cudaFuncSetAttribute(planar_mma_kernel,
                         cudaFuncAttributeMaxDynamicSharedMemorySize, S_TOTAL);
    planar_mma_kernel<<<NGRID, NTHREADS, S_TOTAL>>>(z, b1, dz, dlog);
}

// round 17
// speedup vs baseline: 1.0657x; 1.0657x over previous
#include <cuda_runtime.h>
#include <cuda_fp16.h>
#include <stdint.h>
#include <math.h>

#define BATCH  65536
#define D_DIM  256
#define W_DIM  1024
#define MTILE  128
#define NTHREADS 512
#define CW     128
#define NCHUNK (W_DIM / CW)    // 8
#define WSCALE 64.0f
#define WINV   (1.0f / 64.0f)

// tail-split: 444 full tiles (128 rows) + 136 half tiles (64 rows)
#define NFULL  444
#define NHALF  136
#define NGRID  (NFULL + NHALF)            // 580
#define ROWS_FULL_TOTAL (NFULL * MTILE)   // 56832

// device scratch: weights scaled fp16 (z is converted in-kernel)
__device__ __align__(16) __half g_w1s[W_DIM * D_DIM];   // W1 * 64
__device__ __align__(16) __half g_w2s[D_DIM * W_DIM];   // W2 * 64
__device__ float g_M[W_DIM];

// ---------------- SMEM layout (bytes), XOR-swizzled, pad-free ----------------
#define Z_S    0
#define W1_S   65536
#define W2_S   131072
#define H_S    196608
#define TR_OFF 229376
#define S_TOTAL 229888

// ---------------- PTX helpers ----------------
__device__ __forceinline__ uint32_t smem_u32(const void* p) {
    uint32_t a;
    asm("{ .reg .u64 t; cvta.to.shared.u64 t, %1; cvt.u32.u64 %0, t; }" : "=r"(a) : "l"(p));
    return a;
}
#define CP_ASYNC16(d, s) \
    asm volatile("cp.async.cg.shared.global [%0], [%1], 16;" :: "r"(d), "l"(s))
#define CP_COMMIT() asm volatile("cp.async.commit_group;")
#define CP_WAIT0()  asm volatile("cp.async.wait_group 0;")
#define CP_WAIT1()  asm volatile("cp.async.wait_group 1;")

#define LDSM4(r, addr) \
    asm volatile("ldmatrix.sync.aligned.m8n8.x4.shared.b16 {%0,%1,%2,%3}, [%4];" \
        : "=r"((r)[0]), "=r"((r)[1]), "=r"((r)[2]), "=r"((r)[3]) : "r"(addr))

__device__ __forceinline__ void mma_f16(float* c, const uint32_t* a, uint32_t b0, uint32_t b1) {
    asm volatile(
        "mma.sync.aligned.m16n8k16.row.col.f32.f16.f16.f32 "
        "{%0,%1,%2,%3}, {%4,%5,%6,%7}, {%8,%9}, {%0,%1,%2,%3};"
        : "+f"(c[0]), "+f"(c[1]), "+f"(c[2]), "+f"(c[3])
        : "r"(a[0]), "r"(a[1]), "r"(a[2]), "r"(a[3]), "r"(b0), "r"(b1));
}

// ---------------- fused prepass: weights conv + M, ONE launch ----------------
// blocks [0,256): convert W1+W2 (65536 uint4 items, 256/block)
// blocks [256,1280): compute M[j], j = bid-256
#define WCONV_BLOCKS 256

union PackH8 { uint4 u; __half h[8]; };

__global__ void prep_kernel(const float* __restrict__ W1,
                            const float* __restrict__ W2) {
    if (blockIdx.x < WCONV_BLOCKS) {
        size_t gid = (size_t)blockIdx.x * 256 + threadIdx.x;   // 65536 items
        const float* src;
        __half* dst;
        size_t idx;
        if (gid < 32768) { src = W1; dst = g_w1s; idx = gid; }
        else             { src = W2; dst = g_w2s; idx = gid - 32768; }
        const float4* s = reinterpret_cast<const float4*>(src);
        float4 a = s[idx * 2], b = s[idx * 2 + 1];
        float v[8] = {a.x, a.y, a.z, a.w, b.x, b.y, b.z, b.w};
        PackH8 o;
        #pragma unroll
        for (int i = 0; i < 8; i++) o.h[i] = __float2half_rn(v[i] * WSCALE);
        reinterpret_cast<uint4*>(dst)[idx] = o.u;
    } else {
        int j = blockIdx.x - WCONV_BLOCKS, i = threadIdx.x;
        float v = W1[j * D_DIM + i] * W2[(size_t)i * W_DIM + j];
        #pragma unroll
        for (int o = 16; o > 0; o >>= 1) v += __shfl_down_sync(0xffffffffu, v, o);
        __shared__ float red[8];
        if ((i & 31) == 0) red[i >> 5] = v;
        __syncthreads();
        if (i < 8) {
            float s = red[i];
            #pragma unroll
            for (int o = 4; o > 0; o >>= 1) s += __shfl_down_sync(0xffu, s, o);
            if (i == 0) g_M[j] = s;
        }
    }
}

// ---------------- copy helpers (cp.async, 512 threads, swizzled dst) ---------
// nrows x 256 fp16 (512B rows)
__device__ __forceinline__ void cp_tile512(uint32_t sdst, const __half* g, int nrows) {
    const int total = nrows * 32;
    for (int i = threadIdx.x; i < total; i += NTHREADS) {
        int r = i >> 5, cu = i & 31;
        CP_ASYNC16(sdst + r * 512 + ((cu ^ (r & 7)) << 4), g + r * 256 + cu * 8);
    }
}
// 256 rows x 128 fp16 (256B rows), src rows stride W_DIM
__device__ __forceinline__ void cp_tileW2(uint32_t sdst, const __half* g) {
    for (int i = threadIdx.x; i < 4096; i += NTHREADS) {
        int r = i >> 4, cu = i & 15;
        CP_ASYNC16(sdst + r * 256 + ((cu ^ (r & 7)) << 4), g + (size_t)r * W_DIM + cu * 8);
    }
}

// ---------------- main fused kernel ----------------
__global__ void __launch_bounds__(NTHREADS, 1)
planar_mma_kernel(const float* __restrict__ z,
                  const float* __restrict__ b1,
                  float* __restrict__ dz_out,
                  float* __restrict__ dlog_out) {
    extern __shared__ char smem[];
    const uint32_t sb = smem_u32(smem);
    float* sTr = reinterpret_cast<float*>(smem + TR_OFF);

    const int tid  = threadIdx.x;
    const int wid  = tid >> 5;
    const int lane = tid & 31;
    const int mg   = wid >> 2;     // 0..3 : rows 32*mg .. +31
    const int ng   = wid & 3;      // GEMM1: 32 cols; GEMM2: 64 cols

    // tail-split tile mapping
    const int bid = blockIdx.x;
    int row0, ra;
    if (bid < NFULL) { row0 = bid * MTILE;                          ra = MTILE; }
    else             { row0 = ROWS_FULL_TOTAL + (bid - NFULL) * 64; ra = 64; }
    const bool act = (mg * 32) < ra;   // warp-uniform

    if (tid < MTILE) sTr[tid] = 0.0f;

    // prologue: weights via cp.async; z fp32 -> fp16 converted inline (overlaps)
    cp_tile512(sb + W1_S, g_w1s, 128);
    cp_tileW2(sb + W2_S, g_w2s);
    CP_COMMIT();
    {
        const float4* zg = reinterpret_cast<const float4*>(z + (size_t)row0 * D_DIM);
        const int total = ra * 32;
        for (int i = tid; i < total; i += NTHREADS) {
            int r = i >> 5, cu = i & 31;
            float4 a = zg[r * 64 + cu * 2];
            float4 b = zg[r * 64 + cu * 2 + 1];
            float v[8] = {a.x, a.y, a.z, a.w, b.x, b.y, b.z, b.w};
            PackH8 o;
            #pragma unroll
            for (int q = 0; q < 8; q++) o.h[q] = __float2half_rn(v[q]);
            const uint32_t da = sb + Z_S + r * 512 + ((cu ^ (r & 7)) << 4);
            asm volatile("st.shared.v4.b32 [%0], {%1,%2,%3,%4};"
                :: "r"(da), "r"(o.u.x), "r"(o.u.y), "r"(o.u.z), "r"(o.u.w) : "memory");
        }
    }
    CP_WAIT0();
    __syncthreads();

    // per-lane fragment addressing (XOR swizzle; swz == lane&7 for all reads)
    const int lr    = lane & 15;
    const int kodd  = lane >> 4;
    const int brow  = (lane & 7) + ((lane >> 4) << 3);
    const int koddb = (lane >> 3) & 1;
    const int swz   = lane & 7;

    const uint32_t zbase  = sb + Z_S  + (mg * 32 + lr) * 512;
    const uint32_t w1base = sb + W1_S + (ng * 32 + brow) * 512;
    const uint32_t hbase  = sb + H_S  + (mg * 32 + lr) * 256;
    const uint32_t w2base = sb + W2_S + (ng * 64 + brow) * 256;

    float dz[2][8][4];
    #pragma unroll
    for (int a = 0; a < 2; a++)
        #pragma unroll
        for (int b = 0; b < 8; b++)
            #pragma unroll
            for (int c = 0; c < 4; c++) dz[a][b][c] = 0.0f;
    float tr4[4] = {0.f, 0.f, 0.f, 0.f};

    for (int ch = 0; ch < NCHUNK; ch++) {
        const int jc = ch * CW;

        // ---------- GEMM1: pre = z @ (64*W1chunk)^T, warp m32n32 --------------
        float pre[2][4][4];
        if (act) {
            #pragma unroll
            for (int a = 0; a < 2; a++)
                #pragma unroll
                for (int b = 0; b < 4; b++)
                    #pragma unroll
                    for (int c = 0; c < 4; c++) pre[a][b][c] = 0.0f;

            #pragma unroll 8
            for (int ks = 0; ks < 16; ks++) {
                const uint32_t offA = (uint32_t)(((ks * 2 + kodd)  ^ swz) << 4);
                const uint32_t offB = (uint32_t)(((ks * 2 + koddb) ^ swz) << 4);
                uint32_t ah0[4], ah1[4], bh0[4], bh1[4];
                LDSM4(ah0, zbase + offA);
                LDSM4(ah1, zbase + 16 * 512 + offA);
                LDSM4(bh0, w1base + offB);
                LDSM4(bh1, w1base + 16 * 512 + offB);
                mma_f16(pre[0][0], ah0, bh0[0], bh0[1]);
                mma_f16(pre[0][1], ah0, bh0[2], bh0[3]);
                mma_f16(pre[0][2], ah0, bh1[0], bh1[1]);
                mma_f16(pre[0][3], ah0, bh1[2], bh1[3]);
                mma_f16(pre[1][0], ah1, bh0[0], bh0[1]);
                mma_f16(pre[1][1], ah1, bh0[2], bh0[3]);
                mma_f16(pre[1][2], ah1, bh1[0], bh1[1]);
                mma_f16(pre[1][3], ah1, bh1[2], bh1[3]);
            }

            // -------- epilogue: x = pre/64 + b1; softplus -> h; trace ---------
            #pragma unroll
            for (int mf = 0; mf < 2; mf++) {
                #pragma unroll
                for (int nf = 0; nf < 4; nf++) {
                    const int j0 = jc + ng * 32 + nf * 8 + 2 * (lane & 3);
                    const float b10 = __ldg(&b1[j0]),   b11 = __ldg(&b1[j0 + 1]);
                    const float M0  = g_M[j0],          M1  = g_M[j0 + 1];
                    const int clu = ng * 4 + nf;
                    #pragma unroll
                    for (int bq = 0; bq < 2; bq++) {
                        float x0 = fmaf(pre[mf][nf][2 * bq],     WINV, b10);
                        float x1 = fmaf(pre[mf][nf][2 * bq + 1], WINV, b11);
                        float e0 = __expf(-fabsf(x0)), e1 = __expf(-fabsf(x1));
                        float sp0 = fmaxf(x0, 0.0f) + __logf(1.0f + e0);
                        float sp1 = fmaxf(x1, 0.0f) + __logf(1.0f + e1);
                        float i0 = __fdividef(1.0f, 1.0f + e0);
                        float i1 = __fdividef(1.0f, 1.0f + e1);
                        float sg0 = (x0 >= 0.0f) ? i0 : e0 * i0;
                        float sg1 = (x1 >= 0.0f) ? i1 : e1 * i1;
                        tr4[mf * 2 + bq] = fmaf(sg0, M0, tr4[mf * 2 + bq]);
                        tr4[mf * 2 + bq] = fmaf(sg1, M1, tr4[mf * 2 + bq]);
                        __half h0 = __float2half_rn(sp0);
                        __half h1 = __float2half_rn(sp1);
                        uint32_t phi = ((uint32_t)__half_as_ushort(h1) << 16) |
                                       (uint32_t)__half_as_ushort(h0);
                        const int rl = mg * 32 + mf * 16 + (lane >> 2) + 8 * bq;
                        const uint32_t ha = sb + H_S + rl * 256 +
                                            (((uint32_t)(clu ^ (rl & 7))) << 4) +
                                            (lane & 3) * 4;
                        asm volatile("st.shared.b32 [%0], %1;" :: "r"(ha), "r"(phi) : "memory");
                    }
                }
            }
        }

        // wait for W2(ch) (issued at tail of ch-1; only group in flight)
        CP_WAIT0();
        __syncthreads();   // AB: past GEMM1 (W1 free), h written, W2(ch) visible

        // issue W1(ch+1): hidden under GEMM2(ch)
        if (ch + 1 < NCHUNK) {
            cp_tile512(sb + W1_S, g_w1s + (size_t)(jc + CW) * D_DIM, 128);
            CP_COMMIT();
        }

        // ---------- GEMM2: dz += h @ (64*W2chunk), warp m32n64, K=128 ---------
        if (act) {
            #pragma unroll
            for (int ks = 0; ks < 8; ks++) {
                const uint32_t offA = (uint32_t)(((ks * 2 + kodd)  ^ swz) << 4);
                const uint32_t offB = (uint32_t)(((ks * 2 + koddb) ^ swz) << 4);
                uint32_t ah0[4], ah1[4];
                LDSM4(ah0, hbase + offA);
                LDSM4(ah1, hbase + 16 * 256 + offA);
                #pragma unroll
                for (int t = 0; t < 4; t++) {
                    uint32_t bh[4];
                    LDSM4(bh, w2base + t * 16 * 256 + offB);
                    mma_f16(dz[0][2 * t],     ah0, bh[0], bh[1]);
                    mma_f16(dz[0][2 * t + 1], ah0, bh[2], bh[3]);
                    mma_f16(dz[1][2 * t],     ah1, bh[0], bh[1]);
                    mma_f16(dz[1][2 * t + 1], ah1, bh[2], bh[3]);
                }
            }
        }

        __syncthreads();   // C: all warps past GEMM2 -> W2 buffer free

        // issue W2(ch+1): in flight across chunk boundary; wait only W1(ch+1)
        if (ch + 1 < NCHUNK) {
            cp_tileW2(sb + W2_S, g_w2s + jc + CW);
            CP_COMMIT();
            CP_WAIT1();        // W1(ch+1) done; W2(ch+1) still in flight
            __syncthreads();   // D: W1(ch+1) visible
        }
    }

    // ---------------- writeout (undo weight scale) ----------------
    if (act) {
        #pragma unroll
        for (int mf = 0; mf < 2; mf++) {
            const int rl = mg * 32 + mf * 16 + (lane >> 2);
            #pragma unroll
            for (int nf = 0; nf < 8; nf++) {
                const int col = ng * 64 + nf * 8 + 2 * (lane & 3);
                float2 v0 = make_float2(dz[mf][nf][0] * WINV, dz[mf][nf][1] * WINV);
                float2 v1 = make_float2(dz[mf][nf][2] * WINV, dz[mf][nf][3] * WINV);
                *reinterpret_cast<float2*>(dz_out + (size_t)(row0 + rl) * D_DIM + col) = v0;
                *reinterpret_cast<float2*>(dz_out + (size_t)(row0 + rl + 8) * D_DIM + col) = v1;
            }
        }
        #pragma unroll
        for (int i = 0; i < 4; i++) {
            const int rl = mg * 32 + (i >> 1) * 16 + (lane >> 2) + 8 * (i & 1);
            atomicAdd(&sTr[rl], tr4[i]);
        }
    }
    __syncthreads();
    if (tid < ra) dlog_out[row0 + tid] = -sTr[tid];
}

// ---------------------------------------------------------------------------
extern "C" void kernel_launch(void* const* d_in, const int* in_sizes, int n_in,
                              void* d_out, int out_size) {
    const float* z  = (const float*)d_in[1];
    const float* W1 = (const float*)d_in[2];
    const float* b1 = (const float*)d_in[3];
    const float* W2 = (const float*)d_in[4];

    float* dz   = (float*)d_out;
    float* dlog = dz + (size_t)BATCH * D_DIM;

    prep_kernel<<<WCONV_BLOCKS + W_DIM, 256>>>(W1, W2);

    cudaFuncSetAttribute(planar_mma_kernel,
                         cudaFuncAttributeMaxDynamicSharedMemorySize, S_TOTAL);
    planar_mma_kernel<<<NGRID, NTHREADS, S_TOTAL>>>(z, b1, dz, dlog);
}